// round 8
// baseline (speedup 1.0000x reference)
#include <cuda_runtime.h>
#include <cstdint>

#define DIM   768
#define POOL  20
#define TOPK  9
#define NVEC  6                 // float4 chunks per lane: 768/4/32
#define BLOCKS 444              // 148 SMs x 3 resident CTAs

// Allocation-free scratch (zero-initialized at module load; finalize re-zeros
// them every replay so the graph stays deterministic).
__device__ float        g_rowsum[POOL];
__device__ unsigned int g_count[POOL];
__device__ unsigned int g_done = 0;

// ---------------------------------------------------------------------------
// top-9 on a 20-vector in registers (strict '>' matches lax.top_k ties)
// ---------------------------------------------------------------------------
__device__ __forceinline__ uint64_t topk_pack(float* s)
{
    uint64_t packed = 0;
    #pragma unroll
    for (int t = 0; t < TOPK; t++) {
        float best = -3.4e38f; int bj = 0;
        #pragma unroll
        for (int j = 0; j < POOL; j++)
            if (s[j] > best) { best = s[j]; bj = j; }
        packed |= (uint64_t)bj << (7 * t);
        #pragma unroll
        for (int j = 0; j < POOL; j++)
            if (j == bj) s[j] = -3.4e38f;
    }
    return packed;
}

// ---------------------------------------------------------------------------
// single fused kernel: per-block key-norm prologue, persistent pair loop,
// last-block finalize. No prep launch.
// ---------------------------------------------------------------------------
__global__ void __launch_bounds__(256, 3)
pool_main(const float* __restrict__ x,
          const float* __restrict__ keys,
          const float* __restrict__ prompts,
          const int*   __restrict__ layer,
          float*       __restrict__ out,
          int B, long long total, long long out_sz)
{
    __shared__ float        s_inv[POOL];
    __shared__ unsigned int s_count[POOL];
    __shared__ unsigned int s_last;

    const int warp = threadIdx.x >> 5;
    const int lane = threadIdx.x & 31;

    const float* __restrict__ kbase = keys + (size_t)(*layer) * POOL * DIM;

    if (threadIdx.x < POOL) s_count[threadIdx.x] = 0u;

    // ---- in-block key inverse norms (bit-identical to the old prep) ----
    for (int k = warp; k < POOL; k += 8) {
        const float* __restrict__ krow = kbase + (size_t)k * DIM;
        float ss = 0.f;
        #pragma unroll
        for (int i = 0; i < DIM / 32; i++) {
            float v = __ldg(krow + lane + 32 * i);
            ss += v * v;
        }
        #pragma unroll
        for (int off = 16; off; off >>= 1)
            ss += __shfl_xor_sync(0xffffffffu, ss, off);
        if (lane == 0)
            s_inv[k] = 1.f / fmaxf(sqrtf(ss), 1e-12f);
    }
    __syncthreads();

    const int nwarp = (gridDim.x * blockDim.x) >> 5;
    const int gw    = blockIdx.x * (blockDim.x >> 5) + warp;
    const int npair = (B + 1) >> 1;

    const float4* __restrict__ knv = (const float4*)kbase;
    const float4* __restrict__ pbase =
        (const float4*)(prompts + (size_t)(*layer) * POOL * DIM);

    for (int pair = gw; pair < npair; pair += nwarp) {
        const int r0   = pair * 2;
        const int r1c  = r0 + 1;
        const bool has1 = (r1c < B);
        const int r1   = has1 ? r1c : r0;

        const float4* __restrict__ xr0 = (const float4*)(x + (size_t)r0 * DIM);
        const float4* __restrict__ xr1 = (const float4*)(x + (size_t)r1 * DIM);

        float s0[POOL], s1[POOL];
        #pragma unroll
        for (int j = 0; j < POOL; j++) { s0[j] = 0.f; s1[j] = 0.f; }
        float ss0 = 0.f, ss1 = 0.f;

        #pragma unroll
        for (int i = 0; i < NVEC; i++) {
            const float4 xv0 = __ldcs(xr0 + lane + 32 * i);
            const float4 xv1 = __ldcs(xr1 + lane + 32 * i);
            ss0 += xv0.x * xv0.x + xv0.y * xv0.y + xv0.z * xv0.z + xv0.w * xv0.w;
            ss1 += xv1.x * xv1.x + xv1.y * xv1.y + xv1.z * xv1.z + xv1.w * xv1.w;
            #pragma unroll
            for (int j = 0; j < POOL; j++) {
                const float4 kv = __ldg(knv + j * (DIM / 4) + lane + 32 * i);
                const float invj = s_inv[j];
                // exact replication of old "store normalized key, then FMA":
                // one rounded multiply, then FMA.
                const float knx = __fmul_rn(kv.x, invj);
                const float kny = __fmul_rn(kv.y, invj);
                const float knz = __fmul_rn(kv.z, invj);
                const float knw = __fmul_rn(kv.w, invj);
                s0[j] = __fmaf_rn(xv0.x, knx, s0[j]);
                s0[j] = __fmaf_rn(xv0.y, kny, s0[j]);
                s0[j] = __fmaf_rn(xv0.z, knz, s0[j]);
                s0[j] = __fmaf_rn(xv0.w, knw, s0[j]);
                s1[j] = __fmaf_rn(xv1.x, knx, s1[j]);
                s1[j] = __fmaf_rn(xv1.y, kny, s1[j]);
                s1[j] = __fmaf_rn(xv1.z, knz, s1[j]);
                s1[j] = __fmaf_rn(xv1.w, knw, s1[j]);
            }
        }

        // butterfly reduce all 42 accumulators
        #pragma unroll
        for (int off = 16; off; off >>= 1) {
            ss0 += __shfl_xor_sync(0xffffffffu, ss0, off);
            ss1 += __shfl_xor_sync(0xffffffffu, ss1, off);
            #pragma unroll
            for (int j = 0; j < POOL; j++) {
                s0[j] += __shfl_xor_sync(0xffffffffu, s0[j], off);
                s1[j] += __shfl_xor_sync(0xffffffffu, s1[j], off);
            }
        }

        const float inv0 = 1.f / fmaxf(sqrtf(ss0), 1e-12f);
        const float inv1 = 1.f / fmaxf(sqrtf(ss1), 1e-12f);
        #pragma unroll
        for (int j = 0; j < POOL; j++) { s0[j] *= inv0; s1[j] *= inv1; }

        // dist bookkeeping: pool-sums of sim rows 0..19
        if (lane == 0) {
            if (r0 < POOL) {
                float rs = 0.f;
                #pragma unroll
                for (int j = 0; j < POOL; j++) rs += s0[j];
                g_rowsum[r0] = rs;
            }
            if (has1 && r1 < POOL) {
                float rs = 0.f;
                #pragma unroll
                for (int j = 0; j < POOL; j++) rs += s1[j];
                g_rowsum[r1] = rs;
            }
        }

        const uint64_t p0 = topk_pack(s0);
        const uint64_t p1 = topk_pack(s1);

        if (lane == 0) {
            #pragma unroll
            for (int t = 0; t < TOPK; t++) {
                atomicAdd(&s_count[(int)((p0 >> (7 * t)) & 127)], 1u);
                if (has1)
                    atomicAdd(&s_count[(int)((p1 >> (7 * t)) & 127)], 1u);
            }
        }

        // gather: 18 prompt-row copies, coalesced streaming stores
        float4* __restrict__ o0 = (float4*)out + (size_t)r0 * (TOPK * DIM / 4);
        float4* __restrict__ o1 = (float4*)out + (size_t)r1 * (TOPK * DIM / 4);
        #pragma unroll
        for (int t = 0; t < TOPK; t++) {
            const float4* pr0 = pbase + (int)((p0 >> (7 * t)) & 127) * (DIM / 4);
            #pragma unroll
            for (int i = 0; i < NVEC; i++)
                __stcs(o0 + t * (DIM / 4) + lane + 32 * i, __ldg(pr0 + lane + 32 * i));
        }
        if (has1) {
            #pragma unroll
            for (int t = 0; t < TOPK; t++) {
                const float4* pr1 = pbase + (int)((p1 >> (7 * t)) & 127) * (DIM / 4);
                #pragma unroll
                for (int i = 0; i < NVEC; i++)
                    __stcs(o1 + t * (DIM / 4) + lane + 32 * i, __ldg(pr1 + lane + 32 * i));
            }
        }
    }

    __syncthreads();
    if (threadIdx.x < POOL)
        atomicAdd(&g_count[threadIdx.x], s_count[threadIdx.x]);

    // last-block finalize: dist = 1 - sum_r count[r]*rowsum[r] / (B*9*20)
    __threadfence();
    if (threadIdx.x == 0)
        s_last = (atomicAdd(&g_done, 1u) == gridDim.x - 1) ? 1u : 0u;
    __syncthreads();
    if (s_last && threadIdx.x == 0) {
        double acc = 0.0;
        #pragma unroll
        for (int r = 0; r < POOL; r++)
            acc += (double)g_count[r] * (double)g_rowsum[r];
        const float dist = (float)(1.0 - acc / ((double)B * TOPK * POOL));
        for (long long i = total; i < out_sz; i++) out[i] = dist;
        // reset scratch for the next graph replay
        #pragma unroll
        for (int r = 0; r < POOL; r++) { g_count[r] = 0u; g_rowsum[r] = 0.f; }
        g_done = 0;
    }
}

extern "C" void kernel_launch(void* const* d_in, const int* in_sizes, int n_in,
                              void* d_out, int out_size)
{
    const float* x       = (const float*)d_in[0];
    const float* keys    = (const float*)d_in[1];
    const float* prompts = (const float*)d_in[2];
    const int*   layer   = (const int*)d_in[3];

    const int B = in_sizes[0] / DIM;
    const long long total = (long long)B * TOPK * DIM;

    const int npair  = (B + 1) >> 1;
    int blocks = BLOCKS;
    const int maxblk = (npair + 7) / 8;         // 8 warps per block
    if (blocks > maxblk) blocks = maxblk;

    pool_main<<<blocks, 256>>>(x, keys, prompts, layer, (float*)d_out,
                               B, total, (long long)out_size);
}